// round 10
// baseline (speedup 1.0000x reference)
#include <cuda_runtime.h>
#include <cstdint>

#define IMG_H 1024
#define IMG_W 1024
#define NB 8
#define HW (IMG_H * IMG_W)

#define EPS_G 1e-3f          // gate margin   (fp32 gm err worst-case ~1e-4)
#define EPS_T 1e-3f          // threshold margin vs 2.5 / 5.0
#define EPS_P 1.5e-3f        // orientation perp margin (>= old d*r<1e-3)
#define MAX_FLAGS (1 << 20)

// Scratch (static device globals; no runtime allocation).
__device__ float         g_gmt[HW * NB];          // gm pixel-major [pix][plane]
__device__ unsigned char g_idx[NB * HW];          // ip(3b)|unc(1b)|alt(3b)<<4|force<<7
__device__ float         g_thin[(size_t)NB * HW]; // thin values (fp32, patched by C)
__device__ int           g_flag_count;
__device__ unsigned int  g_flags[MAX_FLAGS];      // b<<20 | y<<10 | x

// neighbor offsets of dir filter k: 0:E 1:SE 2:S 3:SW 4:W 5:NW 6:N 7:NE
__constant__ int c_dy[8] = {0, 1, 1, 1, 0, -1, -1, -1};
__constant__ int c_dx[8] = {1, 1, 0, -1, -1, -1, 0, 1};

// ---------------------------------------------------------------------------
// Compensated (float-float) arithmetic; all _rn so fast-math can't perturb it.
// ---------------------------------------------------------------------------
__device__ __forceinline__ void two_sum(float a, float b, float& s, float& e) {
    s = __fadd_rn(a, b);
    float bv = __fsub_rn(s, a);
    e = __fadd_rn(__fsub_rn(a, __fsub_rn(s, bv)), __fsub_rn(b, bv));
}

struct DAcc { float hi, err; };
__device__ __forceinline__ void dacc_init(DAcc& A) { A.hi = 0.f; A.err = 0.f; }

__device__ __forceinline__ void dacc_fmaff(DAcc& A, float a, float b) {
    float p = __fmul_rn(a, b);
    float e = __fmaf_rn(a, b, -p);
    float s, e2; two_sum(A.hi, p, s, e2);
    A.hi = s;
    A.err = __fadd_rn(A.err, __fadd_rn(e, e2));
}

__device__ __forceinline__ void dacc_fmadf(DAcc& A, float2 v, float w) {
    float p = __fmul_rn(v.x, w);
    float e = __fmaf_rn(v.x, w, -p);
    e = __fmaf_rn(v.y, w, e);
    float s, e2; two_sum(A.hi, p, s, e2);
    A.hi = s;
    A.err = __fadd_rn(A.err, __fadd_rn(e, e2));
}

__device__ __forceinline__ void dacc_adddf(DAcc& A, float2 v) {
    float s, e2; two_sum(A.hi, v.x, s, e2);
    A.hi = s;
    A.err = __fadd_rn(A.err, __fadd_rn(v.y, e2));
}

__device__ __forceinline__ float2 dacc_renorm(const DAcc& A) {
    float hi = __fadd_rn(A.hi, A.err);
    float lo = __fsub_rn(A.err, __fsub_rn(hi, A.hi));
    return make_float2(hi, lo);
}

__device__ __forceinline__ float2 df_add(float2 a, float2 b) {
    float s, e; two_sum(a.x, b.x, s, e);
    e = __fadd_rn(e, __fadd_rn(a.y, b.y));
    float hi = __fadd_rn(s, e);
    float lo = __fsub_rn(e, __fsub_rn(hi, s));
    return make_float2(hi, lo);
}

__device__ __forceinline__ float2 df_sub(float2 a, float2 b) {
    return df_add(a, make_float2(-b.x, -b.y));
}

__device__ __forceinline__ float2 df_scale2(float2 a) {
    return make_float2(__fmul_rn(a.x, 2.f), __fmul_rn(a.y, 2.f));
}

__device__ __forceinline__ float2 df_sqr(float2 a) {
    float p = __fmul_rn(a.x, a.x);
    float e = __fmaf_rn(a.x, a.x, -p);
    e = __fmaf_rn(__fmul_rn(2.f, a.x), a.y, e);
    return make_float2(p, e);
}

__device__ __forceinline__ float2 df_sqrt(float2 a) {
    if (!(a.x > 1e-37f)) {
        float h = a.x > 0.f ? a.x : 0.f;
        return make_float2(__fsqrt_rn(h), 0.f);
    }
    float y = __fsqrt_rn(a.x);
    float p = __fmul_rn(y, y);
    float e = __fmaf_rn(y, y, -p);
    float d = __fsub_rn(a.x, p);
    float num = __fadd_rn(d, __fsub_rn(a.y, e));
    float c = __fdividef(num, __fmul_rn(2.f, y));
    float hi = __fadd_rn(y, c);
    float lo = __fsub_rn(c, __fsub_rn(hi, y));
    return make_float2(hi, lo);
}

// ---------------------------------------------------------------------------
// df64 single-pixel recompute (same operation order as the validated df64 A).
// DIR=false skips the gx/gy accumulators (gate-only calls).
// ---------------------------------------------------------------------------
template <bool DIR>
__device__ void gm_df(const float* __restrict__ img, const float* __restrict__ gv,
                      int q, int y, int x, float& fgm, float& fgx, float& fgy)
{
    DAcc MAG, GXS, GYS;
    dacc_init(MAG); dacc_init(GXS); dacc_init(GYS);

    for (int c = 0; c < 3; ++c) {
        const float* __restrict__ src = img + (size_t)(q * 3 + c) * HW;

        float raw[7][7];
        #pragma unroll
        for (int ry = 0; ry < 7; ++ry) {
            int yy = y - 3 + ry;
            bool rowok = (unsigned)yy < IMG_H;
            #pragma unroll
            for (int rx = 0; rx < 7; ++rx) {
                int xx = x - 3 + rx;
                raw[ry][rx] = (rowok && (unsigned)xx < IMG_W) ? src[yy * IMG_W + xx] : 0.f;
            }
        }

        float2 hb[7][3];
        #pragma unroll
        for (int ry = 0; ry < 7; ++ry) {
            #pragma unroll
            for (int rx = 0; rx < 3; ++rx) {
                DAcc A; dacc_init(A);
                dacc_fmaff(A, gv[0], raw[ry][rx]);
                dacc_fmaff(A, gv[1], raw[ry][rx + 1]);
                dacc_fmaff(A, gv[2], raw[ry][rx + 2]);
                dacc_fmaff(A, gv[3], raw[ry][rx + 3]);
                dacc_fmaff(A, gv[4], raw[ry][rx + 4]);
                hb[ry][rx] = dacc_renorm(A);
            }
        }

        float2 bl[3][3];
        #pragma unroll
        for (int by = 0; by < 3; ++by) {
            int yy = y - 1 + by;
            #pragma unroll
            for (int bx = 0; bx < 3; ++bx) {
                int xx = x - 1 + bx;
                float2 v = make_float2(0.f, 0.f);
                if ((unsigned)yy < IMG_H && (unsigned)xx < IMG_W) {
                    DAcc A; dacc_init(A);
                    dacc_fmadf(A, hb[by][bx],     gv[0]);
                    dacc_fmadf(A, hb[by + 1][bx], gv[1]);
                    dacc_fmadf(A, hb[by + 2][bx], gv[2]);
                    dacc_fmadf(A, hb[by + 3][bx], gv[3]);
                    dacc_fmadf(A, hb[by + 4][bx], gv[4]);
                    v = dacc_renorm(A);
                }
                bl[by][bx] = v;
            }
        }

        float2 gx = df_add(df_add(df_sub(bl[0][0], bl[0][2]), df_sub(bl[2][0], bl[2][2])),
                           df_scale2(df_sub(bl[1][0], bl[1][2])));
        float2 gy = df_add(df_add(df_sub(bl[0][0], bl[2][0]), df_sub(bl[0][2], bl[2][2])),
                           df_scale2(df_sub(bl[0][1], bl[2][1])));

        float2 m = df_sqrt(df_add(df_sqr(gx), df_sqr(gy)));
        dacc_adddf(MAG, m);
        if (DIR) { dacc_adddf(GXS, gx); dacc_adddf(GYS, gy); }
    }
    fgm = dacc_renorm(MAG).x;
    if (DIR) { fgx = dacc_renorm(GXS).x; fgy = dacc_renorm(GYS).x; }
}

// ---------------------------------------------------------------------------
// Kernel A (fp32 fast path): blur+sobel+mag, octant classification (no atan2).
// Loop structure identical to round-9 (do not touch).
// ---------------------------------------------------------------------------
__global__ __launch_bounds__(256) void canny_grad_fp32(
    const float* __restrict__ img, const float* __restrict__ gw)
{
    if (blockIdx.x == 0 && blockIdx.y == 0 && blockIdx.z == 0 &&
        threadIdx.x == 0 && threadIdx.y == 0)
        g_flag_count = 0;          // reset flag list for this pipeline run

    const int b  = blockIdx.z;
    const int x0 = blockIdx.x * 32;
    const int y0 = blockIdx.y * 32;
    const int tid = threadIdx.y * 32 + threadIdx.x;

    __shared__ float s_raw[38][40];
    __shared__ float s_hb[38][36];
    __shared__ float s_bl[34][36];

    const float g0 = gw[0], g1 = gw[1], g2 = gw[2], g3 = gw[3], g4 = gw[4];

    float mag[4] = {0.f, 0.f, 0.f, 0.f};
    float gxs[4] = {0.f, 0.f, 0.f, 0.f};
    float gys[4] = {0.f, 0.f, 0.f, 0.f};

    for (int c = 0; c < 3; ++c) {
        const float* __restrict__ src = img + (size_t)(b * 3 + c) * HW;

        for (int i = tid; i < 38 * 38; i += 256) {
            int r = i / 38, cc = i % 38;
            int gy = y0 - 3 + r, gx = x0 - 3 + cc;
            float v = 0.f;
            if ((unsigned)gy < IMG_H && (unsigned)gx < IMG_W) v = src[gy * IMG_W + gx];
            s_raw[r][cc] = v;
        }
        __syncthreads();

        for (int i = tid; i < 38 * 34; i += 256) {
            int r = i / 34, cc = i % 34;
            s_hb[r][cc] = g0 * s_raw[r][cc] + g1 * s_raw[r][cc + 1] +
                          g2 * s_raw[r][cc + 2] + g3 * s_raw[r][cc + 3] +
                          g4 * s_raw[r][cc + 4];
        }
        __syncthreads();

        for (int i = tid; i < 34 * 34; i += 256) {
            int r = i / 34, cc = i % 34;
            int gy = y0 - 1 + r, gx = x0 - 1 + cc;
            float v = 0.f;
            if ((unsigned)gy < IMG_H && (unsigned)gx < IMG_W)
                v = g0 * s_hb[r][cc] + g1 * s_hb[r + 1][cc] + g2 * s_hb[r + 2][cc] +
                    g3 * s_hb[r + 3][cc] + g4 * s_hb[r + 4][cc];
            s_bl[r][cc] = v;
        }
        __syncthreads();

        const int tx = threadIdx.x;
        #pragma unroll
        for (int k = 0; k < 4; ++k) {
            int row = threadIdx.y + k * 8;
            float b00 = s_bl[row][tx],     b01 = s_bl[row][tx + 1],     b02 = s_bl[row][tx + 2];
            float b10 = s_bl[row + 1][tx],                              b12 = s_bl[row + 1][tx + 2];
            float b20 = s_bl[row + 2][tx], b21 = s_bl[row + 2][tx + 1], b22 = s_bl[row + 2][tx + 2];
            float gx = (b00 - b02) + 2.f * (b10 - b12) + (b20 - b22);
            float gy = (b00 + 2.f * b01 + b02) - (b20 + 2.f * b21 + b22);
            mag[k] += sqrtf(gx * gx + gy * gy);
            gxs[k] += gx;
            gys[k] += gy;
        }
        __syncthreads();
    }

    const int tx = threadIdx.x;
    #pragma unroll
    for (int k = 0; k < 4; ++k) {
        int row = threadIdx.y + k * 8;
        int y = y0 + row, x = x0 + tx;
        int pix = y * IMG_W + x;

        float gx = gxs[k], gy = gys[k];
        float ax = fabsf(gx), ay = fabsf(gy);

        // bucket = rint((atan2(gy,gx)*180/pi+180)/45) & 7, via octant compare.
        // boundaries: ay = tan(22.5)*ax and ay = tan(67.5)*ax per quadrant.
        float p1 = __fmaf_rn(-0.41421356237f, ax, ay);   // ay - tan22.5*ax
        float p2 = __fmaf_rn(-2.41421356237f, ax, ay);   // ay - tan67.5*ax
        int kh = (gx > 0.f) ? 4 : 0;
        int kv = (gy > 0.f) ? 6 : 2;
        int kd = (gx > 0.f) ? ((gy > 0.f) ? 5 : 3) : ((gy > 0.f) ? 7 : 1);
        float perp1 = fabsf(p1) * 0.92387953f;           // cos 22.5
        float perp2 = fabsf(p2) * 0.38268343f;           // cos 67.5
        int ipv, alt;
        if (p2 > 0.f)      { ipv = kv; alt = kd; }
        else if (p1 < 0.f) { ipv = kh; alt = kd; }
        else               { ipv = kd; alt = (perp1 < perp2) ? kh : kv; }
        bool unc   = fminf(perp1, perp2) < EPS_P;
        bool force = (ax < 1e-2f) && (ay < 1e-2f);       // classifier unreliable

        g_gmt[(size_t)pix * NB + b] = mag[k];
        g_idx[(size_t)b * HW + pix] =
            (unsigned char)(ipv | ((unc || force) ? 8 : 0) | (alt << 4) | (force ? 128 : 0));
    }
}

// ---------------------------------------------------------------------------
// Kernel B: NMS + threshold + hysteresis (fp32), thin store + uncertainty flags.
// (round-9 structure; orientation escalation honors the force bit)
// ---------------------------------------------------------------------------
__global__ __launch_bounds__(256) void canny_nms_kernel(float* __restrict__ out)
{
    const int x0 = blockIdx.x * 32;
    const int y0 = blockIdx.y * 32;
    const int tid = threadIdx.y * 32 + threadIdx.x;
    const int tx = threadIdx.x;

    __shared__ float s_gm[NB][36][38];
    __shared__ float s_thin[34][36];

    for (int i = tid; i < 36 * 36; i += 256) {
        int r = i / 36, cc = i % 36;
        int y = y0 - 2 + r, x = x0 - 2 + cc;
        if ((unsigned)y < IMG_H && (unsigned)x < IMG_W) {
            const float4* p = reinterpret_cast<const float4*>(&g_gmt[(size_t)(y * IMG_W + x) * NB]);
            float4 v0 = p[0], v1 = p[1];
            s_gm[0][r][cc] = v0.x; s_gm[1][r][cc] = v0.y;
            s_gm[2][r][cc] = v0.z; s_gm[3][r][cc] = v0.w;
            s_gm[4][r][cc] = v1.x; s_gm[5][r][cc] = v1.y;
            s_gm[6][r][cc] = v1.z; s_gm[7][r][cc] = v1.w;
        } else {
            #pragma unroll
            for (int p = 0; p < 8; ++p) s_gm[p][r][cc] = 0.f;
        }
    }
    __syncthreads();

    for (int b = 0; b < NB; ++b) {
        const int dy = c_dy[b], dx = c_dx[b];

        for (int i = tid; i < 34 * 34; i += 256) {
            int r = i / 34, cc = i % 34;
            int y = y0 - 1 + r, x = x0 - 1 + cc;
            float thin = 0.f;
            if ((unsigned)y < IMG_H && (unsigned)x < IMG_W) {
                int pix = y * IMG_W + x;
                int byte = g_idx[(size_t)b * HW + pix];
                int ip  = byte & 7;
                int in_ = (ip + 4) & 7;
                int gr = r + 1, gc = cc + 1;
                float sp = s_gm[ip][gr][gc]  - s_gm[ip][gr + dy][gc + dx];
                float sn = s_gm[in_][gr][gc] - s_gm[in_][gr + dy][gc + dx];
                float mn = fminf(sp, sn);
                bool gate = mn > 0.f;
                float gmb = s_gm[b][gr][gc];
                if (gate) thin = gmb;

                // core pixels: store thin + flag uncertain decisions
                if (r >= 1 && r <= 32 && cc >= 1 && cc <= 32) {
                    g_thin[(size_t)b * HW + pix] = thin;
                    if (gmb > 2.5f - EPS_T) {       // relevance filter
                        bool unc = (byte & 128) || fabsf(mn) < EPS_G;
                        if (!unc && gate &&
                            (fabsf(gmb - 2.5f) < EPS_T || fabsf(gmb - 5.f) < EPS_T))
                            unc = true;
                        if (!unc && (byte & 8)) {   // orientation near boundary
                            int ia  = (byte >> 4) & 7;
                            int ina = (ia + 4) & 7;
                            float sp2 = s_gm[ia][gr][gc]  - s_gm[ia][gr + dy][gc + dx];
                            float sn2 = s_gm[ina][gr][gc] - s_gm[ina][gr + dy][gc + dx];
                            float mn2 = fminf(sp2, sn2);
                            if ((mn2 > 0.f) != gate || fabsf(mn2) < EPS_G) unc = true;
                        }
                        if (unc) {
                            int s = atomicAdd(&g_flag_count, 1);
                            if (s < MAX_FLAGS)
                                g_flags[s] = ((unsigned)b << 20) | ((unsigned)y << 10) | (unsigned)x;
                        }
                    }
                }
            }
            s_thin[r][cc] = thin;
        }
        __syncthreads();

        #pragma unroll
        for (int k = 0; k < 4; ++k) {
            int ty = threadIdx.y + k * 8;
            int y = y0 + ty, x = x0 + tx;
            float t = s_thin[ty + 1][tx + 1];
            float res;
            if (t > 5.0f) {
                res = 1.f;
            } else if (t >= 2.5f) {
                bool any =
                    s_thin[ty][tx]     > 5.f || s_thin[ty][tx + 1]     > 5.f || s_thin[ty][tx + 2]     > 5.f ||
                    s_thin[ty + 1][tx] > 5.f ||                                 s_thin[ty + 1][tx + 2] > 5.f ||
                    s_thin[ty + 2][tx] > 5.f || s_thin[ty + 2][tx + 1] > 5.f || s_thin[ty + 2][tx + 2] > 5.f;
                res = any ? 1.f : 0.f;
            } else {
                res = 0.f;
            }
            if (y == 0 || y == IMG_H - 1 || x == 0 || x == IMG_W - 1) res = 0.f;
            out[(size_t)b * HW + y * IMG_W + x] = res;
        }
        __syncthreads();
    }
}

// ---------------------------------------------------------------------------
// Kernel C: exact df64 recompute of flagged thin pixels, patch g_thin.
// (uses atan2f on df64-exact gx/gy — the validated ground-truth semantics)
// ---------------------------------------------------------------------------
__global__ __launch_bounds__(256) void canny_fix_kernel(
    const float* __restrict__ img, const float* __restrict__ gw)
{
    int i = blockIdx.x * blockDim.x + threadIdx.x;
    int n = g_flag_count;
    if (n > MAX_FLAGS) n = MAX_FLAGS;
    if (i >= n) return;

    unsigned f = g_flags[i];
    int b = f >> 20, y = (f >> 10) & 1023, x = f & 1023;

    float gv[5];
    #pragma unroll
    for (int k = 0; k < 5; ++k) gv[k] = gw[k];

    float fgm, fgx, fgy;
    gm_df<true>(img, gv, b, y, x, fgm, fgx, fgy);

    float t = atan2f(fgy, fgx);
    float o = __fadd_rn(__fmul_rn(t, 57.29577951308232f), 180.0f);
    float kf = rintf(__fdiv_rn(o, 45.0f));
    int ip  = ((int)kf) & 7;
    int in_ = (ip + 4) & 7;

    int dy = c_dy[b], dx = c_dx[b];
    int y2 = y + dy, x2 = x + dx;
    bool nb_ok = (unsigned)y2 < IMG_H && (unsigned)x2 < IMG_W;

    float dd1, dd2;
    float a0, a1, c0, c1;
    gm_df<false>(img, gv, ip, y, x, a0, dd1, dd2);
    if (nb_ok) gm_df<false>(img, gv, ip, y2, x2, a1, dd1, dd2); else a1 = 0.f;
    gm_df<false>(img, gv, in_, y, x, c0, dd1, dd2);
    if (nb_ok) gm_df<false>(img, gv, in_, y2, x2, c1, dd1, dd2); else c1 = 0.f;

    float sp = __fsub_rn(a0, a1);
    float sn = __fsub_rn(c0, c1);
    float thin = (fminf(sp, sn) > 0.f) ? fgm : 0.f;
    g_thin[(size_t)b * HW + y * IMG_W + x] = thin;
}

// ---------------------------------------------------------------------------
// Kernel D: re-classify 3x3 outputs around each corrected thin pixel.
// ---------------------------------------------------------------------------
__global__ __launch_bounds__(256) void canny_reclass_kernel(float* __restrict__ out)
{
    int i = blockIdx.x * blockDim.x + threadIdx.x;
    int n = g_flag_count;
    if (n > MAX_FLAGS) n = MAX_FLAGS;
    if (i >= n) return;

    unsigned f = g_flags[i];
    int b = f >> 20, y = (f >> 10) & 1023, x = f & 1023;
    const float* tb = &g_thin[(size_t)b * HW];

    #pragma unroll
    for (int dy2 = -1; dy2 <= 1; ++dy2) {
        #pragma unroll
        for (int dx2 = -1; dx2 <= 1; ++dx2) {
            int yo = y + dy2, xo = x + dx2;
            if ((unsigned)yo >= IMG_H || (unsigned)xo >= IMG_W) continue;
            float res = 0.f;
            if (yo > 0 && yo < IMG_H - 1 && xo > 0 && xo < IMG_W - 1) {
                float t = tb[yo * IMG_W + xo];
                if (t > 5.0f) {
                    res = 1.f;
                } else if (t >= 2.5f) {
                    bool any =
                        tb[(yo - 1) * IMG_W + xo - 1] > 5.f || tb[(yo - 1) * IMG_W + xo] > 5.f || tb[(yo - 1) * IMG_W + xo + 1] > 5.f ||
                        tb[yo * IMG_W + xo - 1]       > 5.f ||                                     tb[yo * IMG_W + xo + 1]       > 5.f ||
                        tb[(yo + 1) * IMG_W + xo - 1] > 5.f || tb[(yo + 1) * IMG_W + xo] > 5.f || tb[(yo + 1) * IMG_W + xo + 1] > 5.f;
                    res = any ? 1.f : 0.f;
                }
            }
            out[(size_t)b * HW + yo * IMG_W + xo] = res;
        }
    }
}

// ---------------------------------------------------------------------------
extern "C" void kernel_launch(void* const* d_in, const int* in_sizes, int n_in,
                              void* d_out, int out_size)
{
    const float* img   = (const float*)d_in[0];  // (8,3,1024,1024)
    const float* gauss = (const float*)d_in[1];  // gauss_h (1,1,1,5)
    (void)in_sizes; (void)n_in; (void)out_size;

    dim3 blkA(32, 8);
    dim3 gridA(IMG_W / 32, IMG_H / 32, NB);
    canny_grad_fp32<<<gridA, blkA>>>(img, gauss);

    dim3 blkB(32, 8);
    dim3 gridB(IMG_W / 32, IMG_H / 32);
    canny_nms_kernel<<<gridB, blkB>>>((float*)d_out);

    canny_fix_kernel<<<MAX_FLAGS / 256, 256>>>(img, gauss);
    canny_reclass_kernel<<<MAX_FLAGS / 256, 256>>>((float*)d_out);
}

// round 13
// speedup vs baseline: 1.0600x; 1.0600x over previous
#include <cuda_runtime.h>
#include <cstdint>

#define IMG_H 1024
#define IMG_W 1024
#define NB 8
#define HW (IMG_H * IMG_W)

#define EPS_G 1e-3f          // gate margin   (fp32 gm err worst-case ~1e-4)
#define EPS_T 1e-3f          // threshold margin vs 2.5 / 5.0
#define EPS_O 1e-3f          // orientation margin (d * |grad|)
#define MAX_FLAGS (1 << 20)

// Scratch (static device globals; no runtime allocation).
__device__ float         g_gmt[HW * NB];          // gm pixel-major [pix][plane]
__device__ unsigned char g_idx[NB * HW];          // ip(3b) | unc(1b) | alt(3b)<<4
__device__ float         g_thin[(size_t)NB * HW]; // thin values (fp32, patched by C)
__device__ int           g_flag_count;
__device__ unsigned int  g_flags[MAX_FLAGS];      // b<<20 | y<<10 | x

// neighbor offsets of dir filter k: 0:E 1:SE 2:S 3:SW 4:W 5:NW 6:N 7:NE
__constant__ int c_dy[8] = {0, 1, 1, 1, 0, -1, -1, -1};
__constant__ int c_dx[8] = {1, 1, 0, -1, -1, -1, 0, 1};

// Incremental 2D cursor over a linear strided loop: produces the exact same
// (row, col) sequence as r=i/W, c=i%W for i = tid, tid+256, ... — without the
// per-iteration div/mod (IMAD-chain) cost.
#define CURSOR_INIT(W)  int cur_r = tid / (W), cur_c = tid % (W)
#define CURSOR_STEP(W, Q, REM) \
    do { cur_r += (Q); cur_c += (REM); \
         if (cur_c >= (W)) { cur_c -= (W); ++cur_r; } } while (0)

// ---------------------------------------------------------------------------
// Compensated (float-float) arithmetic; all _rn so fast-math can't perturb it.
// ---------------------------------------------------------------------------
__device__ __forceinline__ void two_sum(float a, float b, float& s, float& e) {
    s = __fadd_rn(a, b);
    float bv = __fsub_rn(s, a);
    e = __fadd_rn(__fsub_rn(a, __fsub_rn(s, bv)), __fsub_rn(b, bv));
}

struct DAcc { float hi, err; };
__device__ __forceinline__ void dacc_init(DAcc& A) { A.hi = 0.f; A.err = 0.f; }

__device__ __forceinline__ void dacc_fmaff(DAcc& A, float a, float b) {
    float p = __fmul_rn(a, b);
    float e = __fmaf_rn(a, b, -p);
    float s, e2; two_sum(A.hi, p, s, e2);
    A.hi = s;
    A.err = __fadd_rn(A.err, __fadd_rn(e, e2));
}

__device__ __forceinline__ void dacc_fmadf(DAcc& A, float2 v, float w) {
    float p = __fmul_rn(v.x, w);
    float e = __fmaf_rn(v.x, w, -p);
    e = __fmaf_rn(v.y, w, e);
    float s, e2; two_sum(A.hi, p, s, e2);
    A.hi = s;
    A.err = __fadd_rn(A.err, __fadd_rn(e, e2));
}

__device__ __forceinline__ void dacc_adddf(DAcc& A, float2 v) {
    float s, e2; two_sum(A.hi, v.x, s, e2);
    A.hi = s;
    A.err = __fadd_rn(A.err, __fadd_rn(v.y, e2));
}

__device__ __forceinline__ float2 dacc_renorm(const DAcc& A) {
    float hi = __fadd_rn(A.hi, A.err);
    float lo = __fsub_rn(A.err, __fsub_rn(hi, A.hi));
    return make_float2(hi, lo);
}

__device__ __forceinline__ float2 df_add(float2 a, float2 b) {
    float s, e; two_sum(a.x, b.x, s, e);
    e = __fadd_rn(e, __fadd_rn(a.y, b.y));
    float hi = __fadd_rn(s, e);
    float lo = __fsub_rn(e, __fsub_rn(hi, s));
    return make_float2(hi, lo);
}

__device__ __forceinline__ float2 df_sub(float2 a, float2 b) {
    return df_add(a, make_float2(-b.x, -b.y));
}

__device__ __forceinline__ float2 df_scale2(float2 a) {
    return make_float2(__fmul_rn(a.x, 2.f), __fmul_rn(a.y, 2.f));
}

__device__ __forceinline__ float2 df_sqr(float2 a) {
    float p = __fmul_rn(a.x, a.x);
    float e = __fmaf_rn(a.x, a.x, -p);
    e = __fmaf_rn(__fmul_rn(2.f, a.x), a.y, e);
    return make_float2(p, e);
}

__device__ __forceinline__ float2 df_sqrt(float2 a) {
    if (!(a.x > 1e-37f)) {
        float h = a.x > 0.f ? a.x : 0.f;
        return make_float2(__fsqrt_rn(h), 0.f);
    }
    float y = __fsqrt_rn(a.x);
    float p = __fmul_rn(y, y);
    float e = __fmaf_rn(y, y, -p);
    float d = __fsub_rn(a.x, p);
    float num = __fadd_rn(d, __fsub_rn(a.y, e));
    float c = __fdividef(num, __fmul_rn(2.f, y));
    float hi = __fadd_rn(y, c);
    float lo = __fsub_rn(c, __fsub_rn(hi, y));
    return make_float2(hi, lo);
}

// ---------------------------------------------------------------------------
// df64 single-pixel recompute (same operation order as the validated df64 A).
// DIR=false skips the gx/gy accumulators (gate-only calls).
// ---------------------------------------------------------------------------
template <bool DIR>
__device__ void gm_df(const float* __restrict__ img, const float* __restrict__ gv,
                      int q, int y, int x, float& fgm, float& fgx, float& fgy)
{
    DAcc MAG, GXS, GYS;
    dacc_init(MAG); dacc_init(GXS); dacc_init(GYS);

    for (int c = 0; c < 3; ++c) {
        const float* __restrict__ src = img + (size_t)(q * 3 + c) * HW;

        float raw[7][7];
        #pragma unroll
        for (int ry = 0; ry < 7; ++ry) {
            int yy = y - 3 + ry;
            bool rowok = (unsigned)yy < IMG_H;
            #pragma unroll
            for (int rx = 0; rx < 7; ++rx) {
                int xx = x - 3 + rx;
                raw[ry][rx] = (rowok && (unsigned)xx < IMG_W) ? src[yy * IMG_W + xx] : 0.f;
            }
        }

        float2 hb[7][3];
        #pragma unroll
        for (int ry = 0; ry < 7; ++ry) {
            #pragma unroll
            for (int rx = 0; rx < 3; ++rx) {
                DAcc A; dacc_init(A);
                dacc_fmaff(A, gv[0], raw[ry][rx]);
                dacc_fmaff(A, gv[1], raw[ry][rx + 1]);
                dacc_fmaff(A, gv[2], raw[ry][rx + 2]);
                dacc_fmaff(A, gv[3], raw[ry][rx + 3]);
                dacc_fmaff(A, gv[4], raw[ry][rx + 4]);
                hb[ry][rx] = dacc_renorm(A);
            }
        }

        float2 bl[3][3];
        #pragma unroll
        for (int by = 0; by < 3; ++by) {
            int yy = y - 1 + by;
            #pragma unroll
            for (int bx = 0; bx < 3; ++bx) {
                int xx = x - 1 + bx;
                float2 v = make_float2(0.f, 0.f);
                if ((unsigned)yy < IMG_H && (unsigned)xx < IMG_W) {
                    DAcc A; dacc_init(A);
                    dacc_fmadf(A, hb[by][bx],     gv[0]);
                    dacc_fmadf(A, hb[by + 1][bx], gv[1]);
                    dacc_fmadf(A, hb[by + 2][bx], gv[2]);
                    dacc_fmadf(A, hb[by + 3][bx], gv[3]);
                    dacc_fmadf(A, hb[by + 4][bx], gv[4]);
                    v = dacc_renorm(A);
                }
                bl[by][bx] = v;
            }
        }

        float2 gx = df_add(df_add(df_sub(bl[0][0], bl[0][2]), df_sub(bl[2][0], bl[2][2])),
                           df_scale2(df_sub(bl[1][0], bl[1][2])));
        float2 gy = df_add(df_add(df_sub(bl[0][0], bl[2][0]), df_sub(bl[0][2], bl[2][2])),
                           df_scale2(df_sub(bl[0][1], bl[2][1])));

        float2 m = df_sqrt(df_add(df_sqr(gx), df_sqr(gy)));
        dacc_adddf(MAG, m);
        if (DIR) { dacc_adddf(GXS, gx); dacc_adddf(GYS, gy); }
    }
    fgm = dacc_renorm(MAG).x;
    if (DIR) { fgx = dacc_renorm(GXS).x; fgy = dacc_renorm(GYS).x; }
}

// ---------------------------------------------------------------------------
// Kernel A (fp32 fast path): blur+sobel+mag/orient (atan2 epilogue, round-9).
// Hot loops use incremental cursors instead of div/mod; identical iteration
// order and memory access pattern.
// ---------------------------------------------------------------------------
__global__ __launch_bounds__(256) void canny_grad_fp32(
    const float* __restrict__ img, const float* __restrict__ gw)
{
    if (blockIdx.x == 0 && blockIdx.y == 0 && blockIdx.z == 0 &&
        threadIdx.x == 0 && threadIdx.y == 0)
        g_flag_count = 0;          // reset flag list for this pipeline run

    const int b  = blockIdx.z;
    const int x0 = blockIdx.x * 32;
    const int y0 = blockIdx.y * 32;
    const int tid = threadIdx.y * 32 + threadIdx.x;

    __shared__ float s_raw[38][40];
    __shared__ float s_hb[38][36];
    __shared__ float s_bl[34][36];

    const float g0 = gw[0], g1 = gw[1], g2 = gw[2], g3 = gw[3], g4 = gw[4];

    float mag[4] = {0.f, 0.f, 0.f, 0.f};
    float gxs[4] = {0.f, 0.f, 0.f, 0.f};
    float gys[4] = {0.f, 0.f, 0.f, 0.f};

    for (int c = 0; c < 3; ++c) {
        const float* __restrict__ src = img + (size_t)(b * 3 + c) * HW;

        {   // raw 38x38, zero padded (W=38, stride 256 = 6*38+28)
            CURSOR_INIT(38);
            while (cur_r < 38) {
                int gy = y0 - 3 + cur_r, gx = x0 - 3 + cur_c;
                float v = 0.f;
                if ((unsigned)gy < IMG_H && (unsigned)gx < IMG_W) v = src[gy * IMG_W + gx];
                s_raw[cur_r][cur_c] = v;
                CURSOR_STEP(38, 6, 28);
            }
        }
        __syncthreads();

        {   // hblur 38x34 (W=34, stride 256 = 7*34+18)
            CURSOR_INIT(34);
            while (cur_r < 38) {
                s_hb[cur_r][cur_c] = g0 * s_raw[cur_r][cur_c] + g1 * s_raw[cur_r][cur_c + 1] +
                                     g2 * s_raw[cur_r][cur_c + 2] + g3 * s_raw[cur_r][cur_c + 3] +
                                     g4 * s_raw[cur_r][cur_c + 4];
                CURSOR_STEP(34, 7, 18);
            }
        }
        __syncthreads();

        {   // vblur 34x34; sobel sees zeros OOB -> force 0
            CURSOR_INIT(34);
            while (cur_r < 34) {
                int gy = y0 - 1 + cur_r, gx = x0 - 1 + cur_c;
                float v = 0.f;
                if ((unsigned)gy < IMG_H && (unsigned)gx < IMG_W)
                    v = g0 * s_hb[cur_r][cur_c] + g1 * s_hb[cur_r + 1][cur_c] +
                        g2 * s_hb[cur_r + 2][cur_c] + g3 * s_hb[cur_r + 3][cur_c] +
                        g4 * s_hb[cur_r + 4][cur_c];
                s_bl[cur_r][cur_c] = v;
                CURSOR_STEP(34, 7, 18);
            }
        }
        __syncthreads();

        const int tx = threadIdx.x;
        #pragma unroll
        for (int k = 0; k < 4; ++k) {
            int row = threadIdx.y + k * 8;
            float b00 = s_bl[row][tx],     b01 = s_bl[row][tx + 1],     b02 = s_bl[row][tx + 2];
            float b10 = s_bl[row + 1][tx],                              b12 = s_bl[row + 1][tx + 2];
            float b20 = s_bl[row + 2][tx], b21 = s_bl[row + 2][tx + 1], b22 = s_bl[row + 2][tx + 2];
            float gx = (b00 - b02) + 2.f * (b10 - b12) + (b20 - b22);
            float gy = (b00 + 2.f * b01 + b02) - (b20 + 2.f * b21 + b22);
            mag[k] += sqrtf(gx * gx + gy * gy);
            gxs[k] += gx;
            gys[k] += gy;
        }
        __syncthreads();
    }

    const int tx = threadIdx.x;
    #pragma unroll
    for (int k = 0; k < 4; ++k) {
        int row = threadIdx.y + k * 8;
        int y = y0 + row, x = x0 + tx;
        int pix = y * IMG_W + x;

        float t = atan2f(gys[k], gxs[k]);
        float o = t * 57.29577951308232f + 180.0f;
        float u = o / 45.0f;
        float kf = rintf(u);
        int ip = ((int)kf) & 7;

        // orientation margin: distance of u to the bucket boundary (half-int)
        float fl = floorf(u);
        float d  = fabsf((u - fl) - 0.5f);
        float r  = sqrtf(gxs[k] * gxs[k] + gys[k] * gys[k]);
        bool unc = (d * r < EPS_O) || (d < 4e-5f);
        int iplo = ((int)fl) & 7;
        int iphi = ((int)fl + 1) & 7;
        int alt  = (ip == iplo) ? iphi : iplo;

        g_gmt[(size_t)pix * NB + b] = mag[k];
        g_idx[(size_t)b * HW + pix] =
            (unsigned char)(ip | (unc ? 8 : 0) | (alt << 4));
    }
}

// ---------------------------------------------------------------------------
// Kernel B: NMS + threshold + hysteresis (fp32), thin store + uncertainty flags.
// (round-9 structure; cursors replace div/mod)
// ---------------------------------------------------------------------------
__global__ __launch_bounds__(256) void canny_nms_kernel(float* __restrict__ out)
{
    const int x0 = blockIdx.x * 32;
    const int y0 = blockIdx.y * 32;
    const int tid = threadIdx.y * 32 + threadIdx.x;
    const int tx = threadIdx.x;

    __shared__ float s_gm[NB][36][38];
    __shared__ float s_thin[34][36];

    {   // stage 36x36 region of all 8 planes (W=36, stride 256 = 7*36+4)
        CURSOR_INIT(36);
        while (cur_r < 36) {
            int y = y0 - 2 + cur_r, x = x0 - 2 + cur_c;
            if ((unsigned)y < IMG_H && (unsigned)x < IMG_W) {
                const float4* p = reinterpret_cast<const float4*>(&g_gmt[(size_t)(y * IMG_W + x) * NB]);
                float4 v0 = p[0], v1 = p[1];
                s_gm[0][cur_r][cur_c] = v0.x; s_gm[1][cur_r][cur_c] = v0.y;
                s_gm[2][cur_r][cur_c] = v0.z; s_gm[3][cur_r][cur_c] = v0.w;
                s_gm[4][cur_r][cur_c] = v1.x; s_gm[5][cur_r][cur_c] = v1.y;
                s_gm[6][cur_r][cur_c] = v1.z; s_gm[7][cur_r][cur_c] = v1.w;
            } else {
                #pragma unroll
                for (int p = 0; p < 8; ++p) s_gm[p][cur_r][cur_c] = 0.f;
            }
            CURSOR_STEP(36, 7, 4);
        }
    }
    __syncthreads();

    for (int b = 0; b < NB; ++b) {
        const int dy = c_dy[b], dx = c_dx[b];

        {   // thin 34x34 (W=34, stride 256 = 7*34+18)
            CURSOR_INIT(34);
            while (cur_r < 34) {
                int r = cur_r, cc = cur_c;
                int y = y0 - 1 + r, x = x0 - 1 + cc;
                float thin = 0.f;
                if ((unsigned)y < IMG_H && (unsigned)x < IMG_W) {
                    int pix = y * IMG_W + x;
                    int byte = g_idx[(size_t)b * HW + pix];
                    int ip  = byte & 7;
                    int in_ = (ip + 4) & 7;
                    int gr = r + 1, gc = cc + 1;
                    float sp = s_gm[ip][gr][gc]  - s_gm[ip][gr + dy][gc + dx];
                    float sn = s_gm[in_][gr][gc] - s_gm[in_][gr + dy][gc + dx];
                    float mn = fminf(sp, sn);
                    bool gate = mn > 0.f;
                    float gmb = s_gm[b][gr][gc];
                    if (gate) thin = gmb;

                    // core pixels: store thin + flag uncertain decisions
                    if (r >= 1 && r <= 32 && cc >= 1 && cc <= 32) {
                        g_thin[(size_t)b * HW + pix] = thin;
                        if (gmb > 2.5f - EPS_T) {       // relevance filter
                            bool unc = fabsf(mn) < EPS_G;
                            if (!unc && gate &&
                                (fabsf(gmb - 2.5f) < EPS_T || fabsf(gmb - 5.f) < EPS_T))
                                unc = true;
                            if (!unc && (byte & 8)) {   // orientation near boundary
                                int ia  = (byte >> 4) & 7;
                                int ina = (ia + 4) & 7;
                                float sp2 = s_gm[ia][gr][gc]  - s_gm[ia][gr + dy][gc + dx];
                                float sn2 = s_gm[ina][gr][gc] - s_gm[ina][gr + dy][gc + dx];
                                float mn2 = fminf(sp2, sn2);
                                if ((mn2 > 0.f) != gate || fabsf(mn2) < EPS_G) unc = true;
                            }
                            if (unc) {
                                int s = atomicAdd(&g_flag_count, 1);
                                if (s < MAX_FLAGS)
                                    g_flags[s] = ((unsigned)b << 20) | ((unsigned)y << 10) | (unsigned)x;
                            }
                        }
                    }
                }
                s_thin[r][cc] = thin;
                CURSOR_STEP(34, 7, 18);
            }
        }
        __syncthreads();

        #pragma unroll
        for (int k = 0; k < 4; ++k) {
            int ty = threadIdx.y + k * 8;
            int y = y0 + ty, x = x0 + tx;
            float t = s_thin[ty + 1][tx + 1];
            float res;
            if (t > 5.0f) {
                res = 1.f;
            } else if (t >= 2.5f) {
                bool any =
                    s_thin[ty][tx]     > 5.f || s_thin[ty][tx + 1]     > 5.f || s_thin[ty][tx + 2]     > 5.f ||
                    s_thin[ty + 1][tx] > 5.f ||                                 s_thin[ty + 1][tx + 2] > 5.f ||
                    s_thin[ty + 2][tx] > 5.f || s_thin[ty + 2][tx + 1] > 5.f || s_thin[ty + 2][tx + 2] > 5.f;
                res = any ? 1.f : 0.f;
            } else {
                res = 0.f;
            }
            if (y == 0 || y == IMG_H - 1 || x == 0 || x == IMG_W - 1) res = 0.f;
            out[(size_t)b * HW + y * IMG_W + x] = res;
        }
        __syncthreads();
    }
}

// ---------------------------------------------------------------------------
// Kernel C: exact df64 recompute of flagged thin pixels, patch g_thin.
// ---------------------------------------------------------------------------
__global__ __launch_bounds__(256) void canny_fix_kernel(
    const float* __restrict__ img, const float* __restrict__ gw)
{
    int i = blockIdx.x * blockDim.x + threadIdx.x;
    int n = g_flag_count;
    if (n > MAX_FLAGS) n = MAX_FLAGS;
    if (i >= n) return;

    unsigned f = g_flags[i];
    int b = f >> 20, y = (f >> 10) & 1023, x = f & 1023;

    float gv[5];
    #pragma unroll
    for (int k = 0; k < 5; ++k) gv[k] = gw[k];

    float fgm, fgx, fgy;
    gm_df<true>(img, gv, b, y, x, fgm, fgx, fgy);

    float t = atan2f(fgy, fgx);
    float o = __fadd_rn(__fmul_rn(t, 57.29577951308232f), 180.0f);
    float kf = rintf(__fdiv_rn(o, 45.0f));
    int ip  = ((int)kf) & 7;
    int in_ = (ip + 4) & 7;

    int dy = c_dy[b], dx = c_dx[b];
    int y2 = y + dy, x2 = x + dx;
    bool nb_ok = (unsigned)y2 < IMG_H && (unsigned)x2 < IMG_W;

    float dd1, dd2;
    float a0, a1, c0, c1;
    gm_df<false>(img, gv, ip, y, x, a0, dd1, dd2);
    if (nb_ok) gm_df<false>(img, gv, ip, y2, x2, a1, dd1, dd2); else a1 = 0.f;
    gm_df<false>(img, gv, in_, y, x, c0, dd1, dd2);
    if (nb_ok) gm_df<false>(img, gv, in_, y2, x2, c1, dd1, dd2); else c1 = 0.f;

    float sp = __fsub_rn(a0, a1);
    float sn = __fsub_rn(c0, c1);
    float thin = (fminf(sp, sn) > 0.f) ? fgm : 0.f;
    g_thin[(size_t)b * HW + y * IMG_W + x] = thin;
}

// ---------------------------------------------------------------------------
// Kernel D: re-classify 3x3 outputs around each corrected thin pixel.
// ---------------------------------------------------------------------------
__global__ __launch_bounds__(256) void canny_reclass_kernel(float* __restrict__ out)
{
    int i = blockIdx.x * blockDim.x + threadIdx.x;
    int n = g_flag_count;
    if (n > MAX_FLAGS) n = MAX_FLAGS;
    if (i >= n) return;

    unsigned f = g_flags[i];
    int b = f >> 20, y = (f >> 10) & 1023, x = f & 1023;
    const float* tb = &g_thin[(size_t)b * HW];

    #pragma unroll
    for (int dy2 = -1; dy2 <= 1; ++dy2) {
        #pragma unroll
        for (int dx2 = -1; dx2 <= 1; ++dx2) {
            int yo = y + dy2, xo = x + dx2;
            if ((unsigned)yo >= IMG_H || (unsigned)xo >= IMG_W) continue;
            float res = 0.f;
            if (yo > 0 && yo < IMG_H - 1 && xo > 0 && xo < IMG_W - 1) {
                float t = tb[yo * IMG_W + xo];
                if (t > 5.0f) {
                    res = 1.f;
                } else if (t >= 2.5f) {
                    bool any =
                        tb[(yo - 1) * IMG_W + xo - 1] > 5.f || tb[(yo - 1) * IMG_W + xo] > 5.f || tb[(yo - 1) * IMG_W + xo + 1] > 5.f ||
                        tb[yo * IMG_W + xo - 1]       > 5.f ||                                     tb[yo * IMG_W + xo + 1]       > 5.f ||
                        tb[(yo + 1) * IMG_W + xo - 1] > 5.f || tb[(yo + 1) * IMG_W + xo] > 5.f || tb[(yo + 1) * IMG_W + xo + 1] > 5.f;
                    res = any ? 1.f : 0.f;
                }
            }
            out[(size_t)b * HW + yo * IMG_W + xo] = res;
        }
    }
}

// ---------------------------------------------------------------------------
extern "C" void kernel_launch(void* const* d_in, const int* in_sizes, int n_in,
                              void* d_out, int out_size)
{
    const float* img   = (const float*)d_in[0];  // (8,3,1024,1024)
    const float* gauss = (const float*)d_in[1];  // gauss_h (1,1,1,5)
    (void)in_sizes; (void)n_in; (void)out_size;

    dim3 blkA(32, 8);
    dim3 gridA(IMG_W / 32, IMG_H / 32, NB);
    canny_grad_fp32<<<gridA, blkA>>>(img, gauss);

    dim3 blkB(32, 8);
    dim3 gridB(IMG_W / 32, IMG_H / 32);
    canny_nms_kernel<<<gridB, blkB>>>((float*)d_out);

    canny_fix_kernel<<<MAX_FLAGS / 256, 256>>>(img, gauss);
    canny_reclass_kernel<<<MAX_FLAGS / 256, 256>>>((float*)d_out);
}

// round 14
// speedup vs baseline: 1.0787x; 1.0177x over previous
#include <cuda_runtime.h>
#include <cstdint>

#define IMG_H 1024
#define IMG_W 1024
#define NB 8
#define HW (IMG_H * IMG_W)

#define EPS_G 1e-3f          // gate margin   (fp32 gm err worst-case ~1e-4)
#define EPS_T 1e-3f          // threshold margin vs 2.5 / 5.0
#define EPS_O 1e-3f          // orientation margin (d * |grad|)
#define MAX_FLAGS (1 << 20)

// Scratch (static device globals; no runtime allocation).
__device__ float         g_gmt[HW * NB];          // gm pixel-major [pix][plane]
__device__ unsigned char g_idx[NB * HW];          // ip(3b) | unc(1b) | alt(3b)<<4
__device__ float         g_thin[(size_t)NB * HW]; // thin values (fp32, patched by C)
__device__ int           g_flag_count;
__device__ unsigned int  g_flags[MAX_FLAGS];      // b<<20 | y<<10 | x

// neighbor offsets of dir filter k: 0:E 1:SE 2:S 3:SW 4:W 5:NW 6:N 7:NE
__constant__ int c_dy[8] = {0, 1, 1, 1, 0, -1, -1, -1};
__constant__ int c_dx[8] = {1, 1, 0, -1, -1, -1, 0, 1};

// Incremental 2D cursor over a linear strided loop (same sequence as
// r=i/W, c=i%W for i = tid, tid+256, ... without per-iteration div/mod).
#define CURSOR_INIT(W)  int cur_r = tid / (W), cur_c = tid % (W)
#define CURSOR_STEP(W, Q, REM) \
    do { cur_r += (Q); cur_c += (REM); \
         if (cur_c >= (W)) { cur_c -= (W); ++cur_r; } } while (0)

// ---------------------------------------------------------------------------
// Compensated (float-float) arithmetic; all _rn so fast-math can't perturb it.
// ---------------------------------------------------------------------------
__device__ __forceinline__ void two_sum(float a, float b, float& s, float& e) {
    s = __fadd_rn(a, b);
    float bv = __fsub_rn(s, a);
    e = __fadd_rn(__fsub_rn(a, __fsub_rn(s, bv)), __fsub_rn(b, bv));
}

struct DAcc { float hi, err; };
__device__ __forceinline__ void dacc_init(DAcc& A) { A.hi = 0.f; A.err = 0.f; }

__device__ __forceinline__ void dacc_fmaff(DAcc& A, float a, float b) {
    float p = __fmul_rn(a, b);
    float e = __fmaf_rn(a, b, -p);
    float s, e2; two_sum(A.hi, p, s, e2);
    A.hi = s;
    A.err = __fadd_rn(A.err, __fadd_rn(e, e2));
}

__device__ __forceinline__ void dacc_fmadf(DAcc& A, float2 v, float w) {
    float p = __fmul_rn(v.x, w);
    float e = __fmaf_rn(v.x, w, -p);
    e = __fmaf_rn(v.y, w, e);
    float s, e2; two_sum(A.hi, p, s, e2);
    A.hi = s;
    A.err = __fadd_rn(A.err, __fadd_rn(e, e2));
}

__device__ __forceinline__ void dacc_adddf(DAcc& A, float2 v) {
    float s, e2; two_sum(A.hi, v.x, s, e2);
    A.hi = s;
    A.err = __fadd_rn(A.err, __fadd_rn(v.y, e2));
}

__device__ __forceinline__ float2 dacc_renorm(const DAcc& A) {
    float hi = __fadd_rn(A.hi, A.err);
    float lo = __fsub_rn(A.err, __fsub_rn(hi, A.hi));
    return make_float2(hi, lo);
}

__device__ __forceinline__ float2 df_add(float2 a, float2 b) {
    float s, e; two_sum(a.x, b.x, s, e);
    e = __fadd_rn(e, __fadd_rn(a.y, b.y));
    float hi = __fadd_rn(s, e);
    float lo = __fsub_rn(e, __fsub_rn(hi, s));
    return make_float2(hi, lo);
}

__device__ __forceinline__ float2 df_sub(float2 a, float2 b) {
    return df_add(a, make_float2(-b.x, -b.y));
}

__device__ __forceinline__ float2 df_scale2(float2 a) {
    return make_float2(__fmul_rn(a.x, 2.f), __fmul_rn(a.y, 2.f));
}

__device__ __forceinline__ float2 df_sqr(float2 a) {
    float p = __fmul_rn(a.x, a.x);
    float e = __fmaf_rn(a.x, a.x, -p);
    e = __fmaf_rn(__fmul_rn(2.f, a.x), a.y, e);
    return make_float2(p, e);
}

__device__ __forceinline__ float2 df_sqrt(float2 a) {
    if (!(a.x > 1e-37f)) {
        float h = a.x > 0.f ? a.x : 0.f;
        return make_float2(__fsqrt_rn(h), 0.f);
    }
    float y = __fsqrt_rn(a.x);
    float p = __fmul_rn(y, y);
    float e = __fmaf_rn(y, y, -p);
    float d = __fsub_rn(a.x, p);
    float num = __fadd_rn(d, __fsub_rn(a.y, e));
    float c = __fdividef(num, __fmul_rn(2.f, y));
    float hi = __fadd_rn(y, c);
    float lo = __fsub_rn(c, __fsub_rn(hi, y));
    return make_float2(hi, lo);
}

// ---------------------------------------------------------------------------
// df64 single-pixel recompute (validated ground-truth semantics).
// DIR=false skips the gx/gy accumulators (gate-only calls).
// ---------------------------------------------------------------------------
template <bool DIR>
__device__ void gm_df(const float* __restrict__ img, const float* __restrict__ gv,
                      int q, int y, int x, float& fgm, float& fgx, float& fgy)
{
    DAcc MAG, GXS, GYS;
    dacc_init(MAG); dacc_init(GXS); dacc_init(GYS);

    for (int c = 0; c < 3; ++c) {
        const float* __restrict__ src = img + (size_t)(q * 3 + c) * HW;

        float raw[7][7];
        #pragma unroll
        for (int ry = 0; ry < 7; ++ry) {
            int yy = y - 3 + ry;
            bool rowok = (unsigned)yy < IMG_H;
            #pragma unroll
            for (int rx = 0; rx < 7; ++rx) {
                int xx = x - 3 + rx;
                raw[ry][rx] = (rowok && (unsigned)xx < IMG_W) ? src[yy * IMG_W + xx] : 0.f;
            }
        }

        float2 hb[7][3];
        #pragma unroll
        for (int ry = 0; ry < 7; ++ry) {
            #pragma unroll
            for (int rx = 0; rx < 3; ++rx) {
                DAcc A; dacc_init(A);
                dacc_fmaff(A, gv[0], raw[ry][rx]);
                dacc_fmaff(A, gv[1], raw[ry][rx + 1]);
                dacc_fmaff(A, gv[2], raw[ry][rx + 2]);
                dacc_fmaff(A, gv[3], raw[ry][rx + 3]);
                dacc_fmaff(A, gv[4], raw[ry][rx + 4]);
                hb[ry][rx] = dacc_renorm(A);
            }
        }

        float2 bl[3][3];
        #pragma unroll
        for (int by = 0; by < 3; ++by) {
            int yy = y - 1 + by;
            #pragma unroll
            for (int bx = 0; bx < 3; ++bx) {
                int xx = x - 1 + bx;
                float2 v = make_float2(0.f, 0.f);
                if ((unsigned)yy < IMG_H && (unsigned)xx < IMG_W) {
                    DAcc A; dacc_init(A);
                    dacc_fmadf(A, hb[by][bx],     gv[0]);
                    dacc_fmadf(A, hb[by + 1][bx], gv[1]);
                    dacc_fmadf(A, hb[by + 2][bx], gv[2]);
                    dacc_fmadf(A, hb[by + 3][bx], gv[3]);
                    dacc_fmadf(A, hb[by + 4][bx], gv[4]);
                    v = dacc_renorm(A);
                }
                bl[by][bx] = v;
            }
        }

        float2 gx = df_add(df_add(df_sub(bl[0][0], bl[0][2]), df_sub(bl[2][0], bl[2][2])),
                           df_scale2(df_sub(bl[1][0], bl[1][2])));
        float2 gy = df_add(df_add(df_sub(bl[0][0], bl[2][0]), df_sub(bl[0][2], bl[2][2])),
                           df_scale2(df_sub(bl[0][1], bl[2][1])));

        float2 m = df_sqrt(df_add(df_sqr(gx), df_sqr(gy)));
        dacc_adddf(MAG, m);
        if (DIR) { dacc_adddf(GXS, gx); dacc_adddf(GYS, gy); }
    }
    fgm = dacc_renorm(MAG).x;
    if (DIR) { fgx = dacc_renorm(GXS).x; fgy = dacc_renorm(GYS).x; }
}

// ---------------------------------------------------------------------------
// Kernel A (fp32 fast path): software-pipelined channels.
//   raw ping-pong (load c+1 overlaps hblur c), fused vblur/sobel over 3
//   channels. Per-channel math + accumulation order identical to round 13
//   -> bit-identical gm/idx.
// ---------------------------------------------------------------------------
__global__ __launch_bounds__(256) void canny_grad_fp32(
    const float* __restrict__ img, const float* __restrict__ gw)
{
    if (blockIdx.x == 0 && blockIdx.y == 0 && blockIdx.z == 0 &&
        threadIdx.x == 0 && threadIdx.y == 0)
        g_flag_count = 0;          // reset flag list for this pipeline run

    const int b  = blockIdx.z;
    const int x0 = blockIdx.x * 32;
    const int y0 = blockIdx.y * 32;
    const int tid = threadIdx.y * 32 + threadIdx.x;

    __shared__ float s_raw[2][38][40];   // ping-pong raw, halo 3
    __shared__ float s_hb[3][38][36];    // h-blurred, all channels
    __shared__ float s_bl[3][34][36];    // fully blurred, all channels

    const float g0 = gw[0], g1 = gw[1], g2 = gw[2], g3 = gw[3], g4 = gw[4];

    float mag[4] = {0.f, 0.f, 0.f, 0.f};
    float gxs[4] = {0.f, 0.f, 0.f, 0.f};
    float gys[4] = {0.f, 0.f, 0.f, 0.f};

    const float* __restrict__ base = img + (size_t)(b * 3) * HW;

    // prologue: load channel 0 raw into buffer 0
    {
        CURSOR_INIT(38);
        while (cur_r < 38) {
            int gy = y0 - 3 + cur_r, gx = x0 - 3 + cur_c;
            float v = 0.f;
            if ((unsigned)gy < IMG_H && (unsigned)gx < IMG_W) v = base[gy * IMG_W + gx];
            s_raw[0][cur_r][cur_c] = v;
            CURSOR_STEP(38, 6, 28);
        }
    }
    __syncthreads();

    // pipelined: hblur c (from buf c&1)  ||  load raw c+1 (into buf (c+1)&1)
    #pragma unroll
    for (int c = 0; c < 3; ++c) {
        const int cb = c & 1;
        {   // hblur 38x34 from s_raw[cb] into s_hb[c]
            CURSOR_INIT(34);
            while (cur_r < 38) {
                s_hb[c][cur_r][cur_c] =
                    g0 * s_raw[cb][cur_r][cur_c]     + g1 * s_raw[cb][cur_r][cur_c + 1] +
                    g2 * s_raw[cb][cur_r][cur_c + 2] + g3 * s_raw[cb][cur_r][cur_c + 3] +
                    g4 * s_raw[cb][cur_r][cur_c + 4];
                CURSOR_STEP(34, 7, 18);
            }
        }
        if (c < 2) {   // overlap: load next channel's raw into the other buffer
            const float* __restrict__ src = base + (size_t)(c + 1) * HW;
            const int nb_ = (c + 1) & 1;
            CURSOR_INIT(38);
            while (cur_r < 38) {
                int gy = y0 - 3 + cur_r, gx = x0 - 3 + cur_c;
                float v = 0.f;
                if ((unsigned)gy < IMG_H && (unsigned)gx < IMG_W) v = src[gy * IMG_W + gx];
                s_raw[nb_][cur_r][cur_c] = v;
                CURSOR_STEP(38, 6, 28);
            }
        }
        __syncthreads();
    }

    {   // vblur 34x34, all 3 channels fused (15 independent LDS chains/item)
        CURSOR_INIT(34);
        while (cur_r < 34) {
            int gy = y0 - 1 + cur_r, gx = x0 - 1 + cur_c;
            bool ok = (unsigned)gy < IMG_H && (unsigned)gx < IMG_W;
            #pragma unroll
            for (int c = 0; c < 3; ++c) {
                float v = 0.f;
                if (ok)
                    v = g0 * s_hb[c][cur_r][cur_c]     + g1 * s_hb[c][cur_r + 1][cur_c] +
                        g2 * s_hb[c][cur_r + 2][cur_c] + g3 * s_hb[c][cur_r + 3][cur_c] +
                        g4 * s_hb[c][cur_r + 4][cur_c];
                s_bl[c][cur_r][cur_c] = v;
            }
            CURSOR_STEP(34, 7, 18);
        }
    }
    __syncthreads();

    // sobel, channels fused; accumulation order per k is c0,c1,c2 (as before)
    const int tx = threadIdx.x;
    #pragma unroll
    for (int k = 0; k < 4; ++k) {
        int row = threadIdx.y + k * 8;
        #pragma unroll
        for (int c = 0; c < 3; ++c) {
            float b00 = s_bl[c][row][tx],     b01 = s_bl[c][row][tx + 1],     b02 = s_bl[c][row][tx + 2];
            float b10 = s_bl[c][row + 1][tx],                                 b12 = s_bl[c][row + 1][tx + 2];
            float b20 = s_bl[c][row + 2][tx], b21 = s_bl[c][row + 2][tx + 1], b22 = s_bl[c][row + 2][tx + 2];
            float gx = (b00 - b02) + 2.f * (b10 - b12) + (b20 - b22);
            float gy = (b00 + 2.f * b01 + b02) - (b20 + 2.f * b21 + b22);
            mag[k] += sqrtf(gx * gx + gy * gy);
            gxs[k] += gx;
            gys[k] += gy;
        }
    }

    #pragma unroll
    for (int k = 0; k < 4; ++k) {
        int row = threadIdx.y + k * 8;
        int y = y0 + row, x = x0 + tx;
        int pix = y * IMG_W + x;

        float t = atan2f(gys[k], gxs[k]);
        float o = t * 57.29577951308232f + 180.0f;
        float u = o / 45.0f;
        float kf = rintf(u);
        int ip = ((int)kf) & 7;

        float fl = floorf(u);
        float d  = fabsf((u - fl) - 0.5f);
        float r  = sqrtf(gxs[k] * gxs[k] + gys[k] * gys[k]);
        bool unc = (d * r < EPS_O) || (d < 4e-5f);
        int iplo = ((int)fl) & 7;
        int iphi = ((int)fl + 1) & 7;
        int alt  = (ip == iplo) ? iphi : iplo;

        g_gmt[(size_t)pix * NB + b] = mag[k];
        g_idx[(size_t)b * HW + pix] =
            (unsigned char)(ip | (unc ? 8 : 0) | (alt << 4));
    }
}

// ---------------------------------------------------------------------------
// Kernel B: NMS + threshold + hysteresis (fp32), thin store + uncertainty flags.
// (round-13 version verbatim)
// ---------------------------------------------------------------------------
__global__ __launch_bounds__(256) void canny_nms_kernel(float* __restrict__ out)
{
    const int x0 = blockIdx.x * 32;
    const int y0 = blockIdx.y * 32;
    const int tid = threadIdx.y * 32 + threadIdx.x;
    const int tx = threadIdx.x;

    __shared__ float s_gm[NB][36][38];
    __shared__ float s_thin[34][36];

    {   // stage 36x36 region of all 8 planes (W=36, stride 256 = 7*36+4)
        CURSOR_INIT(36);
        while (cur_r < 36) {
            int y = y0 - 2 + cur_r, x = x0 - 2 + cur_c;
            if ((unsigned)y < IMG_H && (unsigned)x < IMG_W) {
                const float4* p = reinterpret_cast<const float4*>(&g_gmt[(size_t)(y * IMG_W + x) * NB]);
                float4 v0 = p[0], v1 = p[1];
                s_gm[0][cur_r][cur_c] = v0.x; s_gm[1][cur_r][cur_c] = v0.y;
                s_gm[2][cur_r][cur_c] = v0.z; s_gm[3][cur_r][cur_c] = v0.w;
                s_gm[4][cur_r][cur_c] = v1.x; s_gm[5][cur_r][cur_c] = v1.y;
                s_gm[6][cur_r][cur_c] = v1.z; s_gm[7][cur_r][cur_c] = v1.w;
            } else {
                #pragma unroll
                for (int p = 0; p < 8; ++p) s_gm[p][cur_r][cur_c] = 0.f;
            }
            CURSOR_STEP(36, 7, 4);
        }
    }
    __syncthreads();

    for (int b = 0; b < NB; ++b) {
        const int dy = c_dy[b], dx = c_dx[b];

        {   // thin 34x34 (W=34, stride 256 = 7*34+18)
            CURSOR_INIT(34);
            while (cur_r < 34) {
                int r = cur_r, cc = cur_c;
                int y = y0 - 1 + r, x = x0 - 1 + cc;
                float thin = 0.f;
                if ((unsigned)y < IMG_H && (unsigned)x < IMG_W) {
                    int pix = y * IMG_W + x;
                    int byte = g_idx[(size_t)b * HW + pix];
                    int ip  = byte & 7;
                    int in_ = (ip + 4) & 7;
                    int gr = r + 1, gc = cc + 1;
                    float sp = s_gm[ip][gr][gc]  - s_gm[ip][gr + dy][gc + dx];
                    float sn = s_gm[in_][gr][gc] - s_gm[in_][gr + dy][gc + dx];
                    float mn = fminf(sp, sn);
                    bool gate = mn > 0.f;
                    float gmb = s_gm[b][gr][gc];
                    if (gate) thin = gmb;

                    if (r >= 1 && r <= 32 && cc >= 1 && cc <= 32) {   // core pixel
                        g_thin[(size_t)b * HW + pix] = thin;
                        if (gmb > 2.5f - EPS_T) {       // relevance filter
                            bool unc = fabsf(mn) < EPS_G;
                            if (!unc && gate &&
                                (fabsf(gmb - 2.5f) < EPS_T || fabsf(gmb - 5.f) < EPS_T))
                                unc = true;
                            if (!unc && (byte & 8)) {   // orientation near boundary
                                int ia  = (byte >> 4) & 7;
                                int ina = (ia + 4) & 7;
                                float sp2 = s_gm[ia][gr][gc]  - s_gm[ia][gr + dy][gc + dx];
                                float sn2 = s_gm[ina][gr][gc] - s_gm[ina][gr + dy][gc + dx];
                                float mn2 = fminf(sp2, sn2);
                                if ((mn2 > 0.f) != gate || fabsf(mn2) < EPS_G) unc = true;
                            }
                            if (unc) {
                                int s = atomicAdd(&g_flag_count, 1);
                                if (s < MAX_FLAGS)
                                    g_flags[s] = ((unsigned)b << 20) | ((unsigned)y << 10) | (unsigned)x;
                            }
                        }
                    }
                }
                s_thin[r][cc] = thin;
                CURSOR_STEP(34, 7, 18);
            }
        }
        __syncthreads();

        #pragma unroll
        for (int k = 0; k < 4; ++k) {
            int ty = threadIdx.y + k * 8;
            int y = y0 + ty, x = x0 + tx;
            float t = s_thin[ty + 1][tx + 1];
            float res;
            if (t > 5.0f) {
                res = 1.f;
            } else if (t >= 2.5f) {
                bool any =
                    s_thin[ty][tx]     > 5.f || s_thin[ty][tx + 1]     > 5.f || s_thin[ty][tx + 2]     > 5.f ||
                    s_thin[ty + 1][tx] > 5.f ||                                 s_thin[ty + 1][tx + 2] > 5.f ||
                    s_thin[ty + 2][tx] > 5.f || s_thin[ty + 2][tx + 1] > 5.f || s_thin[ty + 2][tx + 2] > 5.f;
                res = any ? 1.f : 0.f;
            } else {
                res = 0.f;
            }
            if (y == 0 || y == IMG_H - 1 || x == 0 || x == IMG_W - 1) res = 0.f;
            out[(size_t)b * HW + y * IMG_W + x] = res;
        }
        __syncthreads();
    }
}

// ---------------------------------------------------------------------------
// Kernel C: exact df64 recompute of flagged thin pixels, patch g_thin.
// ---------------------------------------------------------------------------
__global__ __launch_bounds__(256) void canny_fix_kernel(
    const float* __restrict__ img, const float* __restrict__ gw)
{
    int i = blockIdx.x * blockDim.x + threadIdx.x;
    int n = g_flag_count;
    if (n > MAX_FLAGS) n = MAX_FLAGS;
    if (i >= n) return;

    unsigned f = g_flags[i];
    int b = f >> 20, y = (f >> 10) & 1023, x = f & 1023;

    float gv[5];
    #pragma unroll
    for (int k = 0; k < 5; ++k) gv[k] = gw[k];

    float fgm, fgx, fgy;
    gm_df<true>(img, gv, b, y, x, fgm, fgx, fgy);

    float t = atan2f(fgy, fgx);
    float o = __fadd_rn(__fmul_rn(t, 57.29577951308232f), 180.0f);
    float kf = rintf(__fdiv_rn(o, 45.0f));
    int ip  = ((int)kf) & 7;
    int in_ = (ip + 4) & 7;

    int dy = c_dy[b], dx = c_dx[b];
    int y2 = y + dy, x2 = x + dx;
    bool nb_ok = (unsigned)y2 < IMG_H && (unsigned)x2 < IMG_W;

    float dd1, dd2;
    float a0, a1, c0, c1;
    gm_df<false>(img, gv, ip, y, x, a0, dd1, dd2);
    if (nb_ok) gm_df<false>(img, gv, ip, y2, x2, a1, dd1, dd2); else a1 = 0.f;
    gm_df<false>(img, gv, in_, y, x, c0, dd1, dd2);
    if (nb_ok) gm_df<false>(img, gv, in_, y2, x2, c1, dd1, dd2); else c1 = 0.f;

    float sp = __fsub_rn(a0, a1);
    float sn = __fsub_rn(c0, c1);
    float thin = (fminf(sp, sn) > 0.f) ? fgm : 0.f;
    g_thin[(size_t)b * HW + y * IMG_W + x] = thin;
}

// ---------------------------------------------------------------------------
// Kernel D: re-classify 3x3 outputs around each corrected thin pixel.
// ---------------------------------------------------------------------------
__global__ __launch_bounds__(256) void canny_reclass_kernel(float* __restrict__ out)
{
    int i = blockIdx.x * blockDim.x + threadIdx.x;
    int n = g_flag_count;
    if (n > MAX_FLAGS) n = MAX_FLAGS;
    if (i >= n) return;

    unsigned f = g_flags[i];
    int b = f >> 20, y = (f >> 10) & 1023, x = f & 1023;
    const float* tb = &g_thin[(size_t)b * HW];

    #pragma unroll
    for (int dy2 = -1; dy2 <= 1; ++dy2) {
        #pragma unroll
        for (int dx2 = -1; dx2 <= 1; ++dx2) {
            int yo = y + dy2, xo = x + dx2;
            if ((unsigned)yo >= IMG_H || (unsigned)xo >= IMG_W) continue;
            float res = 0.f;
            if (yo > 0 && yo < IMG_H - 1 && xo > 0 && xo < IMG_W - 1) {
                float t = tb[yo * IMG_W + xo];
                if (t > 5.0f) {
                    res = 1.f;
                } else if (t >= 2.5f) {
                    bool any =
                        tb[(yo - 1) * IMG_W + xo - 1] > 5.f || tb[(yo - 1) * IMG_W + xo] > 5.f || tb[(yo - 1) * IMG_W + xo + 1] > 5.f ||
                        tb[yo * IMG_W + xo - 1]       > 5.f ||                                     tb[yo * IMG_W + xo + 1]       > 5.f ||
                        tb[(yo + 1) * IMG_W + xo - 1] > 5.f || tb[(yo + 1) * IMG_W + xo] > 5.f || tb[(yo + 1) * IMG_W + xo + 1] > 5.f;
                    res = any ? 1.f : 0.f;
                }
            }
            out[(size_t)b * HW + yo * IMG_W + xo] = res;
        }
    }
}

// ---------------------------------------------------------------------------
extern "C" void kernel_launch(void* const* d_in, const int* in_sizes, int n_in,
                              void* d_out, int out_size)
{
    const float* img   = (const float*)d_in[0];  // (8,3,1024,1024)
    const float* gauss = (const float*)d_in[1];  // gauss_h (1,1,1,5)
    (void)in_sizes; (void)n_in; (void)out_size;

    dim3 blkA(32, 8);
    dim3 gridA(IMG_W / 32, IMG_H / 32, NB);
    canny_grad_fp32<<<gridA, blkA>>>(img, gauss);

    dim3 blkB(32, 8);
    dim3 gridB(IMG_W / 32, IMG_H / 32);
    canny_nms_kernel<<<gridB, blkB>>>((float*)d_out);

    canny_fix_kernel<<<MAX_FLAGS / 256, 256>>>(img, gauss);
    canny_reclass_kernel<<<MAX_FLAGS / 256, 256>>>((float*)d_out);
}

// round 17
// speedup vs baseline: 1.0847x; 1.0055x over previous
#include <cuda_runtime.h>
#include <cstdint>

#define IMG_H 1024
#define IMG_W 1024
#define NB 8
#define HW (IMG_H * IMG_W)

#define EPS_G 1e-3f          // gate margin   (fp32 gm err worst-case ~1e-4)
#define EPS_T 1e-3f          // threshold margin vs 2.5 / 5.0
#define EPS_O 1e-3f          // orientation margin (d * |grad|)
#define MAX_FLAGS (1 << 20)

// Scratch (static device globals; no runtime allocation).
__device__ float         g_gmt[HW * NB];          // gm pixel-major [pix][plane]
__device__ unsigned char g_idx[NB * HW];          // ip(3b) | unc(1b) | alt(3b)<<4
__device__ float         g_thin[(size_t)NB * HW]; // thin values (fp32, patched by C)
__device__ int           g_flag_count;
__device__ unsigned int  g_flags[MAX_FLAGS];      // b<<20 | y<<10 | x
__device__ int           g_fix_count;             // pixels whose thin CHANGED in C
__device__ unsigned int  g_fixed[MAX_FLAGS];

// neighbor offsets of dir filter k: 0:E 1:SE 2:S 3:SW 4:W 5:NW 6:N 7:NE
__constant__ int c_dy[8] = {0, 1, 1, 1, 0, -1, -1, -1};
__constant__ int c_dx[8] = {1, 1, 0, -1, -1, -1, 0, 1};

// Incremental 2D cursor over a linear strided loop (same sequence as
// r=i/W, c=i%W for i = tid, tid+256, ... without per-iteration div/mod).
#define CURSOR_INIT(W)  int cur_r = tid / (W), cur_c = tid % (W)
#define CURSOR_STEP(W, Q, REM) \
    do { cur_r += (Q); cur_c += (REM); \
         if (cur_c >= (W)) { cur_c -= (W); ++cur_r; } } while (0)

// ---------------------------------------------------------------------------
// Compensated (float-float) arithmetic; all _rn so fast-math can't perturb it.
// ---------------------------------------------------------------------------
__device__ __forceinline__ void two_sum(float a, float b, float& s, float& e) {
    s = __fadd_rn(a, b);
    float bv = __fsub_rn(s, a);
    e = __fadd_rn(__fsub_rn(a, __fsub_rn(s, bv)), __fsub_rn(b, bv));
}

struct DAcc { float hi, err; };
__device__ __forceinline__ void dacc_init(DAcc& A) { A.hi = 0.f; A.err = 0.f; }

__device__ __forceinline__ void dacc_fmaff(DAcc& A, float a, float b) {
    float p = __fmul_rn(a, b);
    float e = __fmaf_rn(a, b, -p);
    float s, e2; two_sum(A.hi, p, s, e2);
    A.hi = s;
    A.err = __fadd_rn(A.err, __fadd_rn(e, e2));
}

__device__ __forceinline__ void dacc_fmadf(DAcc& A, float2 v, float w) {
    float p = __fmul_rn(v.x, w);
    float e = __fmaf_rn(v.x, w, -p);
    e = __fmaf_rn(v.y, w, e);
    float s, e2; two_sum(A.hi, p, s, e2);
    A.hi = s;
    A.err = __fadd_rn(A.err, __fadd_rn(e, e2));
}

__device__ __forceinline__ void dacc_adddf(DAcc& A, float2 v) {
    float s, e2; two_sum(A.hi, v.x, s, e2);
    A.hi = s;
    A.err = __fadd_rn(A.err, __fadd_rn(v.y, e2));
}

__device__ __forceinline__ float2 dacc_renorm(const DAcc& A) {
    float hi = __fadd_rn(A.hi, A.err);
    float lo = __fsub_rn(A.err, __fsub_rn(hi, A.hi));
    return make_float2(hi, lo);
}

__device__ __forceinline__ float2 df_add(float2 a, float2 b) {
    float s, e; two_sum(a.x, b.x, s, e);
    e = __fadd_rn(e, __fadd_rn(a.y, b.y));
    float hi = __fadd_rn(s, e);
    float lo = __fsub_rn(e, __fsub_rn(hi, s));
    return make_float2(hi, lo);
}

__device__ __forceinline__ float2 df_sub(float2 a, float2 b) {
    return df_add(a, make_float2(-b.x, -b.y));
}

__device__ __forceinline__ float2 df_scale2(float2 a) {
    return make_float2(__fmul_rn(a.x, 2.f), __fmul_rn(a.y, 2.f));
}

__device__ __forceinline__ float2 df_sqr(float2 a) {
    float p = __fmul_rn(a.x, a.x);
    float e = __fmaf_rn(a.x, a.x, -p);
    e = __fmaf_rn(__fmul_rn(2.f, a.x), a.y, e);
    return make_float2(p, e);
}

__device__ __forceinline__ float2 df_sqrt(float2 a) {
    if (!(a.x > 1e-37f)) {
        float h = a.x > 0.f ? a.x : 0.f;
        return make_float2(__fsqrt_rn(h), 0.f);
    }
    float y = __fsqrt_rn(a.x);
    float p = __fmul_rn(y, y);
    float e = __fmaf_rn(y, y, -p);
    float d = __fsub_rn(a.x, p);
    float num = __fadd_rn(d, __fsub_rn(a.y, e));
    float c = __fdividef(num, __fmul_rn(2.f, y));
    float hi = __fadd_rn(y, c);
    float lo = __fsub_rn(c, __fsub_rn(hi, y));
    return make_float2(hi, lo);
}

// ---------------------------------------------------------------------------
// df64 single-pixel recompute (validated ground-truth semantics).
// DIR=false skips the gx/gy accumulators (gate-only calls).
// ---------------------------------------------------------------------------
template <bool DIR>
__device__ void gm_df(const float* __restrict__ img, const float* __restrict__ gv,
                      int q, int y, int x, float& fgm, float& fgx, float& fgy)
{
    DAcc MAG, GXS, GYS;
    dacc_init(MAG); dacc_init(GXS); dacc_init(GYS);

    for (int c = 0; c < 3; ++c) {
        const float* __restrict__ src = img + (size_t)(q * 3 + c) * HW;

        float raw[7][7];
        #pragma unroll
        for (int ry = 0; ry < 7; ++ry) {
            int yy = y - 3 + ry;
            bool rowok = (unsigned)yy < IMG_H;
            #pragma unroll
            for (int rx = 0; rx < 7; ++rx) {
                int xx = x - 3 + rx;
                raw[ry][rx] = (rowok && (unsigned)xx < IMG_W) ? src[yy * IMG_W + xx] : 0.f;
            }
        }

        float2 hb[7][3];
        #pragma unroll
        for (int ry = 0; ry < 7; ++ry) {
            #pragma unroll
            for (int rx = 0; rx < 3; ++rx) {
                DAcc A; dacc_init(A);
                dacc_fmaff(A, gv[0], raw[ry][rx]);
                dacc_fmaff(A, gv[1], raw[ry][rx + 1]);
                dacc_fmaff(A, gv[2], raw[ry][rx + 2]);
                dacc_fmaff(A, gv[3], raw[ry][rx + 3]);
                dacc_fmaff(A, gv[4], raw[ry][rx + 4]);
                hb[ry][rx] = dacc_renorm(A);
            }
        }

        float2 bl[3][3];
        #pragma unroll
        for (int by = 0; by < 3; ++by) {
            int yy = y - 1 + by;
            #pragma unroll
            for (int bx = 0; bx < 3; ++bx) {
                int xx = x - 1 + bx;
                float2 v = make_float2(0.f, 0.f);
                if ((unsigned)yy < IMG_H && (unsigned)xx < IMG_W) {
                    DAcc A; dacc_init(A);
                    dacc_fmadf(A, hb[by][bx],     gv[0]);
                    dacc_fmadf(A, hb[by + 1][bx], gv[1]);
                    dacc_fmadf(A, hb[by + 2][bx], gv[2]);
                    dacc_fmadf(A, hb[by + 3][bx], gv[3]);
                    dacc_fmadf(A, hb[by + 4][bx], gv[4]);
                    v = dacc_renorm(A);
                }
                bl[by][bx] = v;
            }
        }

        float2 gx = df_add(df_add(df_sub(bl[0][0], bl[0][2]), df_sub(bl[2][0], bl[2][2])),
                           df_scale2(df_sub(bl[1][0], bl[1][2])));
        float2 gy = df_add(df_add(df_sub(bl[0][0], bl[2][0]), df_sub(bl[0][2], bl[2][2])),
                           df_scale2(df_sub(bl[0][1], bl[2][1])));

        float2 m = df_sqrt(df_add(df_sqr(gx), df_sqr(gy)));
        dacc_adddf(MAG, m);
        if (DIR) { dacc_adddf(GXS, gx); dacc_adddf(GYS, gy); }
    }
    fgm = dacc_renorm(MAG).x;
    if (DIR) { fgx = dacc_renorm(GXS).x; fgy = dacc_renorm(GYS).x; }
}

// ---------------------------------------------------------------------------
// Kernel A (fp32 fast path): software-pipelined channels (round-14 version).
// ---------------------------------------------------------------------------
__global__ __launch_bounds__(256) void canny_grad_fp32(
    const float* __restrict__ img, const float* __restrict__ gw)
{
    if (blockIdx.x == 0 && blockIdx.y == 0 && blockIdx.z == 0 &&
        threadIdx.x == 0 && threadIdx.y == 0) {
        g_flag_count = 0;          // reset repair lists for this pipeline run
        g_fix_count  = 0;
    }

    const int b  = blockIdx.z;
    const int x0 = blockIdx.x * 32;
    const int y0 = blockIdx.y * 32;
    const int tid = threadIdx.y * 32 + threadIdx.x;

    __shared__ float s_raw[2][38][40];   // ping-pong raw, halo 3
    __shared__ float s_hb[3][38][36];    // h-blurred, all channels
    __shared__ float s_bl[3][34][36];    // fully blurred, all channels

    const float g0 = gw[0], g1 = gw[1], g2 = gw[2], g3 = gw[3], g4 = gw[4];

    float mag[4] = {0.f, 0.f, 0.f, 0.f};
    float gxs[4] = {0.f, 0.f, 0.f, 0.f};
    float gys[4] = {0.f, 0.f, 0.f, 0.f};

    const float* __restrict__ base = img + (size_t)(b * 3) * HW;

    {   // prologue: load channel 0 raw into buffer 0
        CURSOR_INIT(38);
        while (cur_r < 38) {
            int gy = y0 - 3 + cur_r, gx = x0 - 3 + cur_c;
            float v = 0.f;
            if ((unsigned)gy < IMG_H && (unsigned)gx < IMG_W) v = base[gy * IMG_W + gx];
            s_raw[0][cur_r][cur_c] = v;
            CURSOR_STEP(38, 6, 28);
        }
    }
    __syncthreads();

    #pragma unroll
    for (int c = 0; c < 3; ++c) {
        const int cb = c & 1;
        {   // hblur 38x34 from s_raw[cb] into s_hb[c]
            CURSOR_INIT(34);
            while (cur_r < 38) {
                s_hb[c][cur_r][cur_c] =
                    g0 * s_raw[cb][cur_r][cur_c]     + g1 * s_raw[cb][cur_r][cur_c + 1] +
                    g2 * s_raw[cb][cur_r][cur_c + 2] + g3 * s_raw[cb][cur_r][cur_c + 3] +
                    g4 * s_raw[cb][cur_r][cur_c + 4];
                CURSOR_STEP(34, 7, 18);
            }
        }
        if (c < 2) {   // overlap: load next channel's raw into the other buffer
            const float* __restrict__ src = base + (size_t)(c + 1) * HW;
            const int nb_ = (c + 1) & 1;
            CURSOR_INIT(38);
            while (cur_r < 38) {
                int gy = y0 - 3 + cur_r, gx = x0 - 3 + cur_c;
                float v = 0.f;
                if ((unsigned)gy < IMG_H && (unsigned)gx < IMG_W) v = src[gy * IMG_W + gx];
                s_raw[nb_][cur_r][cur_c] = v;
                CURSOR_STEP(38, 6, 28);
            }
        }
        __syncthreads();
    }

    {   // vblur 34x34, all 3 channels fused
        CURSOR_INIT(34);
        while (cur_r < 34) {
            int gy = y0 - 1 + cur_r, gx = x0 - 1 + cur_c;
            bool ok = (unsigned)gy < IMG_H && (unsigned)gx < IMG_W;
            #pragma unroll
            for (int c = 0; c < 3; ++c) {
                float v = 0.f;
                if (ok)
                    v = g0 * s_hb[c][cur_r][cur_c]     + g1 * s_hb[c][cur_r + 1][cur_c] +
                        g2 * s_hb[c][cur_r + 2][cur_c] + g3 * s_hb[c][cur_r + 3][cur_c] +
                        g4 * s_hb[c][cur_r + 4][cur_c];
                s_bl[c][cur_r][cur_c] = v;
            }
            CURSOR_STEP(34, 7, 18);
        }
    }
    __syncthreads();

    const int tx = threadIdx.x;
    #pragma unroll
    for (int k = 0; k < 4; ++k) {
        int row = threadIdx.y + k * 8;
        #pragma unroll
        for (int c = 0; c < 3; ++c) {
            float b00 = s_bl[c][row][tx],     b01 = s_bl[c][row][tx + 1],     b02 = s_bl[c][row][tx + 2];
            float b10 = s_bl[c][row + 1][tx],                                 b12 = s_bl[c][row + 1][tx + 2];
            float b20 = s_bl[c][row + 2][tx], b21 = s_bl[c][row + 2][tx + 1], b22 = s_bl[c][row + 2][tx + 2];
            float gx = (b00 - b02) + 2.f * (b10 - b12) + (b20 - b22);
            float gy = (b00 + 2.f * b01 + b02) - (b20 + 2.f * b21 + b22);
            mag[k] += sqrtf(gx * gx + gy * gy);
            gxs[k] += gx;
            gys[k] += gy;
        }
    }

    #pragma unroll
    for (int k = 0; k < 4; ++k) {
        int row = threadIdx.y + k * 8;
        int y = y0 + row, x = x0 + tx;
        int pix = y * IMG_W + x;

        float t = atan2f(gys[k], gxs[k]);
        float o = t * 57.29577951308232f + 180.0f;
        float u = o / 45.0f;
        float kf = rintf(u);
        int ip = ((int)kf) & 7;

        float fl = floorf(u);
        float d  = fabsf((u - fl) - 0.5f);
        float r  = sqrtf(gxs[k] * gxs[k] + gys[k] * gys[k]);
        bool unc = (d * r < EPS_O) || (d < 4e-5f);
        int iplo = ((int)fl) & 7;
        int iphi = ((int)fl + 1) & 7;
        int alt  = (ip == iplo) ? iphi : iplo;

        g_gmt[(size_t)pix * NB + b] = mag[k];
        g_idx[(size_t)b * HW + pix] =
            (unsigned char)(ip | (unc ? 8 : 0) | (alt << 4));
    }
}

// ---------------------------------------------------------------------------
// Kernel B: NMS + threshold + hysteresis (fp32), thin store + uncertainty flags.
// (round-13/14 version verbatim — while-loop thin pass, bounded compile)
// ---------------------------------------------------------------------------
__global__ __launch_bounds__(256) void canny_nms_kernel(float* __restrict__ out)
{
    const int x0 = blockIdx.x * 32;
    const int y0 = blockIdx.y * 32;
    const int tid = threadIdx.y * 32 + threadIdx.x;
    const int tx = threadIdx.x;

    __shared__ float s_gm[NB][36][38];
    __shared__ float s_thin[34][36];

    {   // stage 36x36 region of all 8 planes (W=36, stride 256 = 7*36+4)
        CURSOR_INIT(36);
        while (cur_r < 36) {
            int y = y0 - 2 + cur_r, x = x0 - 2 + cur_c;
            if ((unsigned)y < IMG_H && (unsigned)x < IMG_W) {
                const float4* p = reinterpret_cast<const float4*>(&g_gmt[(size_t)(y * IMG_W + x) * NB]);
                float4 v0 = p[0], v1 = p[1];
                s_gm[0][cur_r][cur_c] = v0.x; s_gm[1][cur_r][cur_c] = v0.y;
                s_gm[2][cur_r][cur_c] = v0.z; s_gm[3][cur_r][cur_c] = v0.w;
                s_gm[4][cur_r][cur_c] = v1.x; s_gm[5][cur_r][cur_c] = v1.y;
                s_gm[6][cur_r][cur_c] = v1.z; s_gm[7][cur_r][cur_c] = v1.w;
            } else {
                #pragma unroll
                for (int p = 0; p < 8; ++p) s_gm[p][cur_r][cur_c] = 0.f;
            }
            CURSOR_STEP(36, 7, 4);
        }
    }
    __syncthreads();

    for (int b = 0; b < NB; ++b) {
        const int dy = c_dy[b], dx = c_dx[b];

        {   // thin 34x34 (W=34, stride 256 = 7*34+18)
            CURSOR_INIT(34);
            while (cur_r < 34) {
                int r = cur_r, cc = cur_c;
                int y = y0 - 1 + r, x = x0 - 1 + cc;
                float thin = 0.f;
                if ((unsigned)y < IMG_H && (unsigned)x < IMG_W) {
                    int pix = y * IMG_W + x;
                    int byte = g_idx[(size_t)b * HW + pix];
                    int ip  = byte & 7;
                    int in_ = (ip + 4) & 7;
                    int gr = r + 1, gc = cc + 1;
                    float sp = s_gm[ip][gr][gc]  - s_gm[ip][gr + dy][gc + dx];
                    float sn = s_gm[in_][gr][gc] - s_gm[in_][gr + dy][gc + dx];
                    float mn = fminf(sp, sn);
                    bool gate = mn > 0.f;
                    float gmb = s_gm[b][gr][gc];
                    if (gate) thin = gmb;

                    if (r >= 1 && r <= 32 && cc >= 1 && cc <= 32) {   // core pixel
                        g_thin[(size_t)b * HW + pix] = thin;
                        if (gmb > 2.5f - EPS_T) {       // relevance filter
                            bool unc = fabsf(mn) < EPS_G;
                            if (!unc && gate &&
                                (fabsf(gmb - 2.5f) < EPS_T || fabsf(gmb - 5.f) < EPS_T))
                                unc = true;
                            if (!unc && (byte & 8)) {   // orientation near boundary
                                int ia  = (byte >> 4) & 7;
                                int ina = (ia + 4) & 7;
                                float sp2 = s_gm[ia][gr][gc]  - s_gm[ia][gr + dy][gc + dx];
                                float sn2 = s_gm[ina][gr][gc] - s_gm[ina][gr + dy][gc + dx];
                                float mn2 = fminf(sp2, sn2);
                                if ((mn2 > 0.f) != gate || fabsf(mn2) < EPS_G) unc = true;
                            }
                            if (unc) {
                                int s = atomicAdd(&g_flag_count, 1);
                                if (s < MAX_FLAGS)
                                    g_flags[s] = ((unsigned)b << 20) | ((unsigned)y << 10) | (unsigned)x;
                            }
                        }
                    }
                }
                s_thin[r][cc] = thin;
                CURSOR_STEP(34, 7, 18);
            }
        }
        __syncthreads();

        #pragma unroll
        for (int k = 0; k < 4; ++k) {
            int ty = threadIdx.y + k * 8;
            int y = y0 + ty, x = x0 + tx;
            float t = s_thin[ty + 1][tx + 1];
            float res;
            if (t > 5.0f) {
                res = 1.f;
            } else if (t >= 2.5f) {
                bool any =
                    s_thin[ty][tx]     > 5.f || s_thin[ty][tx + 1]     > 5.f || s_thin[ty][tx + 2]     > 5.f ||
                    s_thin[ty + 1][tx] > 5.f ||                                 s_thin[ty + 1][tx + 2] > 5.f ||
                    s_thin[ty + 2][tx] > 5.f || s_thin[ty + 2][tx + 1] > 5.f || s_thin[ty + 2][tx + 2] > 5.f;
                res = any ? 1.f : 0.f;
            } else {
                res = 0.f;
            }
            if (y == 0 || y == IMG_H - 1 || x == 0 || x == IMG_W - 1) res = 0.f;
            out[(size_t)b * HW + y * IMG_W + x] = res;
        }
        __syncthreads();
    }
}

// ---------------------------------------------------------------------------
// Kernel C: exact df64 recompute of flagged thin pixels; records CHANGED ones.
// ---------------------------------------------------------------------------
__global__ __launch_bounds__(256) void canny_fix_kernel(
    const float* __restrict__ img, const float* __restrict__ gw)
{
    int i = blockIdx.x * blockDim.x + threadIdx.x;
    int n = g_flag_count;
    if (n > MAX_FLAGS) n = MAX_FLAGS;
    if (i >= n) return;

    unsigned f = g_flags[i];
    int b = f >> 20, y = (f >> 10) & 1023, x = f & 1023;

    float gv[5];
    #pragma unroll
    for (int k = 0; k < 5; ++k) gv[k] = gw[k];

    float fgm, fgx, fgy;
    gm_df<true>(img, gv, b, y, x, fgm, fgx, fgy);

    float t = atan2f(fgy, fgx);
    float o = __fadd_rn(__fmul_rn(t, 57.29577951308232f), 180.0f);
    float kf = rintf(__fdiv_rn(o, 45.0f));
    int ip  = ((int)kf) & 7;
    int in_ = (ip + 4) & 7;

    int dy = c_dy[b], dx = c_dx[b];
    int y2 = y + dy, x2 = x + dx;
    bool nb_ok = (unsigned)y2 < IMG_H && (unsigned)x2 < IMG_W;

    float dd1, dd2;
    float a0, a1, c0, c1;
    gm_df<false>(img, gv, ip, y, x, a0, dd1, dd2);
    if (nb_ok) gm_df<false>(img, gv, ip, y2, x2, a1, dd1, dd2); else a1 = 0.f;
    gm_df<false>(img, gv, in_, y, x, c0, dd1, dd2);
    if (nb_ok) gm_df<false>(img, gv, in_, y2, x2, c1, dd1, dd2); else c1 = 0.f;

    float sp = __fsub_rn(a0, a1);
    float sn = __fsub_rn(c0, c1);
    float thin = (fminf(sp, sn) > 0.f) ? fgm : 0.f;

    size_t ofs = (size_t)b * HW + y * IMG_W + x;
    float old = g_thin[ofs];
    if (__float_as_uint(thin) != __float_as_uint(old)) {
        g_thin[ofs] = thin;
        int s = atomicAdd(&g_fix_count, 1);
        if (s < MAX_FLAGS) g_fixed[s] = f;
    }
}

// ---------------------------------------------------------------------------
// Kernel D: re-classify 3x3 outputs around each CHANGED thin pixel.
// (unchanged flags need no reclass: B already wrote the same values)
// ---------------------------------------------------------------------------
__global__ __launch_bounds__(256) void canny_reclass_kernel(float* __restrict__ out)
{
    int n = g_fix_count;
    if (n > MAX_FLAGS) n = MAX_FLAGS;

    for (int i = blockIdx.x * blockDim.x + threadIdx.x; i < n;
         i += gridDim.x * blockDim.x) {
        unsigned f = g_fixed[i];
        int b = f >> 20, y = (f >> 10) & 1023, x = f & 1023;
        const float* tb = &g_thin[(size_t)b * HW];

        #pragma unroll
        for (int dy2 = -1; dy2 <= 1; ++dy2) {
            #pragma unroll
            for (int dx2 = -1; dx2 <= 1; ++dx2) {
                int yo = y + dy2, xo = x + dx2;
                if ((unsigned)yo >= IMG_H || (unsigned)xo >= IMG_W) continue;
                float res = 0.f;
                if (yo > 0 && yo < IMG_H - 1 && xo > 0 && xo < IMG_W - 1) {
                    float t = tb[yo * IMG_W + xo];
                    if (t > 5.0f) {
                        res = 1.f;
                    } else if (t >= 2.5f) {
                        bool any =
                            tb[(yo - 1) * IMG_W + xo - 1] > 5.f || tb[(yo - 1) * IMG_W + xo] > 5.f || tb[(yo - 1) * IMG_W + xo + 1] > 5.f ||
                            tb[yo * IMG_W + xo - 1]       > 5.f ||                                    tb[yo * IMG_W + xo + 1]       > 5.f ||
                            tb[(yo + 1) * IMG_W + xo - 1] > 5.f || tb[(yo + 1) * IMG_W + xo] > 5.f || tb[(yo + 1) * IMG_W + xo + 1] > 5.f;
                        res = any ? 1.f : 0.f;
                    }
                }
                out[(size_t)b * HW + yo * IMG_W + xo] = res;
            }
        }
    }
}

// ---------------------------------------------------------------------------
extern "C" void kernel_launch(void* const* d_in, const int* in_sizes, int n_in,
                              void* d_out, int out_size)
{
    const float* img   = (const float*)d_in[0];  // (8,3,1024,1024)
    const float* gauss = (const float*)d_in[1];  // gauss_h (1,1,1,5)
    (void)in_sizes; (void)n_in; (void)out_size;

    dim3 blkA(32, 8);
    dim3 gridA(IMG_W / 32, IMG_H / 32, NB);
    canny_grad_fp32<<<gridA, blkA>>>(img, gauss);

    dim3 blkB(32, 8);
    dim3 gridB(IMG_W / 32, IMG_H / 32);
    canny_nms_kernel<<<gridB, blkB>>>((float*)d_out);

    canny_fix_kernel<<<MAX_FLAGS / 256, 256>>>(img, gauss);
    canny_reclass_kernel<<<512, 256>>>((float*)d_out);
}